// round 15
// baseline (speedup 1.0000x reference)
#include <cuda_runtime.h>
#include <cstddef>

#define TT 9
#define SS 9
#define FF 512
#define H1 32
#define H2 64
#define XROW 1032          // floats per s-pair row (2*FF + 8 pad)
#define BASE7 7.0f

typedef unsigned long long ull;

// ---------------- device scratch ----------------
__device__ float g_W1q [TT * 8 * 8 * 32 * 8];    // rotated W1: [t][w8][g8][lane32][c8]
                                                 // lane=(fh<<3|oq), c=(do<<1|df)
                                                 // f = w*64+g*8+fh*2+df, o = oq*4+do
__device__ float g_W2r [TT * H1];
__device__ float g_mW1p[2 * 8 * 16 * 32 * 4];    // rotated mW1: [hh2][w8][g16][lane32][c4]
                                                 // f = w*64+g*4+fh*2+df, o = 32*hh+op*2+do
__device__ float g_mW2r[H2];
__device__ float g_team[4096 * TT * FF];
__device__ float g_tq  [4096 * TT];
__device__ float g_sink;

// ---------------- profiling-alignment dummies (ncu capture lands on k1) ----------------
__global__ void kalign() {
    if (threadIdx.x == 0xFFFFFFFFu) g_sink = 0.0f;
}

// ---------------- f32x2 helpers ----------------
__device__ __forceinline__ ull ffma2(ull a, ull b, ull c) {
    ull d;
    asm("fma.rn.f32x2 %0, %1, %2, %3;" : "=l"(d) : "l"(a), "l"(b), "l"(c));
    return d;
}
__device__ __forceinline__ ull fadd2(ull a, ull b) {
    ull d;
    asm("add.rn.f32x2 %0, %1, %2;" : "=l"(d) : "l"(a), "l"(b));
    return d;
}
__device__ __forceinline__ ull dup2(float x) {
    ull r;
    asm("mov.b64 %0, {%1, %1};" : "=l"(r) : "f"(x));
    return r;
}
__device__ __forceinline__ float2 u2f(ull r) {
    float2 v;
    asm("mov.b64 {%0, %1}, %2;" : "=f"(v.x), "=f"(v.y) : "l"(r));
    return v;
}

__device__ __forceinline__ float pnorm1(float h, float g, float b) {
    float m = h - BASE7 * floorf(h * (1.0f / BASE7));
    return g * ((m - 3.5f) * (1.0f / 3.5f)) + b;
}

// rotate-absorb: coeff of x_f in dot(rot(x), Wrow)
__device__ __forceinline__ float rotv(const float* __restrict__ Wrow,
                                      const float* __restrict__ ang,
                                      int f, int nplanes) {
    if (f >= 2 * nplanes) return Wrow[f];
    int p = f >> 1; float a = ang[p];
    float c = cosf(a), s = sinf(a);
    float w0 = Wrow[2 * p], w1 = Wrow[2 * p + 1];
    return (f & 1) ? (c * w1 - s * w0) : (c * w0 + s * w1);
}

// ---------------- prep: rotate + re-tile weights ----------------
__global__ void kprep(const float* __restrict__ W1, const float* __restrict__ ang1,
                      const float* __restrict__ W2, const float* __restrict__ ang2,
                      const float* __restrict__ mW1, const float* __restrict__ mang1,
                      const float* __restrict__ mW2, const float* __restrict__ mang2)
{
    int idx = blockIdx.x * 256 + threadIdx.x;
    const int N1 = TT * 16384;     // g_W1q
    const int N2 = TT * H1;        // g_W2r
    const int N3 = 32768;          // g_mW1p
    const int N4 = H2;             // g_mW2r
    if (idx < N1) {
        int c    =  idx        & 7;
        int lane = (idx >> 3)  & 31;
        int g    = (idx >> 8)  & 7;
        int w    = (idx >> 11) & 7;
        int t    =  idx >> 14;
        int oq = lane & 7, fh = lane >> 3;
        int dd = c >> 1, df = c & 1;
        int f = w * 64 + g * 8 + fh * 2 + df;
        int o = oq * 4 + dd;
        g_W1q[idx] = rotv(W1 + ((size_t)t * H1 + o) * FF, ang1 + 2 * t, f, 2);
    } else if (idx < N1 + N2) {
        int jj = idx - N1; int t = jj / H1, o = jj - t * H1;
        g_W2r[jj] = rotv(W2 + t * H1, ang2 + 2 * t, o, 2);
    } else if (idx < N1 + N2 + N3) {
        int jj = idx - N1 - N2;
        int c    =  jj        & 3;
        int lane = (jj >> 2)  & 31;
        int g    = (jj >> 7)  & 15;
        int w    = (jj >> 11) & 7;
        int hh   = (jj >> 14) & 1;
        int op = lane & 15, fh = lane >> 4;
        int df = c >> 1, dd = c & 1;
        int f = w * 64 + g * 4 + fh * 2 + df;
        int o = 32 * hh + op * 2 + dd;
        g_mW1p[jj] = rotv(mW1 + (size_t)o * FF, mang1, f, 4);
    } else if (idx < N1 + N2 + N3 + N4) {
        int o = idx - N1 - N2 - N3;
        g_mW2r[o] = rotv(mW2, mang2, o, 2);
    }
}

// ---------------- kernel 1: per (b,t) — 4-o x 4-fh lanes, 5 padded s-pairs ----------------
__global__ __launch_bounds__(256, 3) void k1(const float* __restrict__ path,
                                             const float* __restrict__ b1,
                                             const float* __restrict__ gamma1,
                                             const float* __restrict__ beta1)
{
    __shared__ float xsp[5 * XROW];          // s-pair rows 0..3 + row4 = (x8, 0)
    __shared__ float psA[8 * 5 * 32 * 2];    // warp partials: [w][sp5][o]{lo,hi}
    __shared__ float scp[SS * 33];           // score partials
    __shared__ float qsm[16];

    const int t = blockIdx.x, b = blockIdx.y;
    const int tid = threadIdx.x, lane = tid & 31, w = tid >> 5;
    const int oq = lane & 7, fh = lane >> 3;

    // zero the pad slots of row 4 (s=9 ghost)
    for (int i = tid; i < FF; i += 256) xsp[4 * XROW + 2 * i + 1] = 0.f;

    // stage x: pair layout (incremental f,s — uniform mapping incl. s=8)
    {
        const float* xb = path + (size_t)b * (FF * TT * SS) + t * SS;
        int f = tid / 9;
        int s = tid - f * 9;
        const float* p = xb + f * (TT * SS) + s;
        #pragma unroll
        for (int it = 0; it < 18; ++it) {
            float v = *p;
            xsp[(s >> 1) * XROW + 2 * f + (s & 1)] = v;
            s += 4; f += 28;
            if (s >= 9) { s -= 9; f += 1; p += 29 * (TT * SS) - 5; }
            else        {                p += 28 * (TT * SS) + 4; }
        }
    }
    __syncthreads();

    // mainloop: lane owns o-quad {4oq..4oq+3}; f = 64w + 8g + 2fh + {0,1}, g = 0..7
    ull acc[4][5];
    #pragma unroll
    for (int oc = 0; oc < 4; ++oc)
        #pragma unroll
        for (int sp = 0; sp < 5; ++sp) acc[oc][sp] = 0ull;

    const float4* wq = reinterpret_cast<const float4*>(g_W1q)
                     + ((size_t)(t * 8 + w) * 8) * 64 + lane * 2;
    const float* xb0 = xsp + 2 * (w * 64 + 2 * fh);

    #pragma unroll
    for (int g = 0; g < 8; ++g) {
        float4 wa = wq[g * 64];          // (do0,df0) (do0,df1) (do1,df0) (do1,df1)
        float4 wb = wq[g * 64 + 1];      // (do2,df0) (do2,df1) (do3,df0) (do3,df1)
        const float* xg = xb0 + 16 * g;
        #pragma unroll
        for (int sp = 0; sp < 5; ++sp) {
            ulonglong2 r = *reinterpret_cast<const ulonglong2*>(xg + sp * XROW);
            acc[0][sp] = ffma2(r.x, dup2(wa.x), acc[0][sp]);
            acc[0][sp] = ffma2(r.y, dup2(wa.y), acc[0][sp]);
            acc[1][sp] = ffma2(r.x, dup2(wa.z), acc[1][sp]);
            acc[1][sp] = ffma2(r.y, dup2(wa.w), acc[1][sp]);
            acc[2][sp] = ffma2(r.x, dup2(wb.x), acc[2][sp]);
            acc[2][sp] = ffma2(r.y, dup2(wb.y), acc[2][sp]);
            acc[3][sp] = ffma2(r.x, dup2(wb.z), acc[3][sp]);
            acc[3][sp] = ffma2(r.y, dup2(wb.w), acc[3][sp]);
        }
    }

    // combine 4 fh groups: xor-8 then xor-16; lanes 0..7 hold warp totals
    #pragma unroll
    for (int rd = 8; rd <= 16; rd <<= 1) {
        #pragma unroll
        for (int oc = 0; oc < 4; ++oc)
            #pragma unroll
            for (int sp = 0; sp < 5; ++sp)
                acc[oc][sp] = fadd2(acc[oc][sp],
                                    __shfl_xor_sync(0xffffffffu, acc[oc][sp], rd));
    }

    if (lane < 8) {
        int ob = 4 * lane;
        #pragma unroll
        for (int sp = 0; sp < 5; ++sp) {
            *reinterpret_cast<ulonglong2*>(&psA[((w * 5 + sp) * 32 + ob) * 2]) =
                make_ulonglong2(acc[0][sp], acc[1][sp]);
            *reinterpret_cast<ulonglong2*>(&psA[((w * 5 + sp) * 32 + ob + 2) * 2]) =
                make_ulonglong2(acc[2][sp], acc[3][sp]);
        }
    }
    __syncthreads();

    // finalize: sum 8 warp-partials -> h -> pnorm -> score partials
    for (int v = tid; v < SS * H1; v += 256) {
        int s = v >> 5, o = v & 31;
        int sp = s >> 1, part = s & 1;     // s=8 -> sp=4, part=0
        float hh = 0.f;
        #pragma unroll
        for (int ww = 0; ww < 8; ++ww)
            hh += psA[((ww * 5 + sp) * 32 + o) * 2 + part];
        hh += b1[t * H1 + o];
        float pn = pnorm1(hh, gamma1[t * H1 + o], beta1[t * H1 + o]);
        scp[s * 33 + o] = pn * g_W2r[t * H1 + o];
    }
    __syncthreads();

    // softmax over s (warp 0)
    if (tid < 32) {
        float sc = -3.0e38f;
        if (lane < SS) {
            float s0 = 0.f;
            #pragma unroll
            for (int o = 0; o < H1; ++o) s0 += scp[lane * 33 + o];
            sc = s0;
        }
        float mx = sc;
        #pragma unroll
        for (int d = 16; d; d >>= 1) mx = fmaxf(mx, __shfl_xor_sync(0xffffffffu, mx, d));
        float e = (lane < SS) ? expf(sc - mx) : 0.f;
        float se = e;
        #pragma unroll
        for (int d = 16; d; d >>= 1) se += __shfl_xor_sync(0xffffffffu, se, d);
        float q = e / se;
        float qt = q;
        #pragma unroll
        for (int d = 16; d; d >>= 1) qt += __shfl_xor_sync(0xffffffffu, qt, d);
        if (lane < SS) qsm[lane] = q;
        if (lane == 0) g_tq[b * TT + t] = qt * (1.0f / SS);
    }
    __syncthreads();

    // team_out[f] = sum_s q[s] * x[s][f]  (f-pair per thread, one pass)
    {
        float* tout = g_team + ((size_t)b * TT + t) * FF;
        float q0 = qsm[0], q1 = qsm[1], q2 = qsm[2], q3 = qsm[3], q4 = qsm[4],
              q5 = qsm[5], q6 = qsm[6], q7 = qsm[7], q8 = qsm[8];
        int f2 = 2 * tid;   // 0..510
        ulonglong2 u0 = *reinterpret_cast<const ulonglong2*>(&xsp[0 * XROW + 2 * f2]);
        ulonglong2 u1 = *reinterpret_cast<const ulonglong2*>(&xsp[1 * XROW + 2 * f2]);
        ulonglong2 u2 = *reinterpret_cast<const ulonglong2*>(&xsp[2 * XROW + 2 * f2]);
        ulonglong2 u3 = *reinterpret_cast<const ulonglong2*>(&xsp[3 * XROW + 2 * f2]);
        ulonglong2 u4 = *reinterpret_cast<const ulonglong2*>(&xsp[4 * XROW + 2 * f2]);
        float2 a4 = u2f(u4.x), b4 = u2f(u4.y);
        float o0 = q8 * a4.x, o1 = q8 * b4.x;
        float2 a;
        a = u2f(u0.x); o0 = fmaf(q0, a.x, o0); o0 = fmaf(q1, a.y, o0);
        a = u2f(u0.y); o1 = fmaf(q0, a.x, o1); o1 = fmaf(q1, a.y, o1);
        a = u2f(u1.x); o0 = fmaf(q2, a.x, o0); o0 = fmaf(q3, a.y, o0);
        a = u2f(u1.y); o1 = fmaf(q2, a.x, o1); o1 = fmaf(q3, a.y, o1);
        a = u2f(u2.x); o0 = fmaf(q4, a.x, o0); o0 = fmaf(q5, a.y, o0);
        a = u2f(u2.y); o1 = fmaf(q4, a.x, o1); o1 = fmaf(q5, a.y, o1);
        a = u2f(u3.x); o0 = fmaf(q6, a.x, o0); o0 = fmaf(q7, a.y, o0);
        a = u2f(u3.y); o1 = fmaf(q6, a.x, o1); o1 = fmaf(q7, a.y, o1);
        *reinterpret_cast<float2*>(&tout[f2]) = make_float2(o0, o1);
    }
}

// ---------------- kernel 2: per b — o-pair lanes, two H2 halves (R14-proven) ----------------
__global__ __launch_bounds__(256, 4) void k2(const float* __restrict__ mb1,
                                             const float* __restrict__ mgamma,
                                             const float* __restrict__ mbeta,
                                             const float* __restrict__ cc,
                                             const float* __restrict__ rc,
                                             const float* __restrict__ ic,
                                             float* __restrict__ out)
{
    __shared__ float tsp[4 * XROW];          // team t-pair rows
    __shared__ float ts8[FF + 8];            // t=8 row
    __shared__ float psA[8 * 4 * 32 * 2];    // warp partials (reused per half)
    __shared__ float ps8[8 * 32];
    __shared__ float msp[9 * 65];            // score partials (full H2)
    __shared__ float mwm[16];

    const int b = blockIdx.x;
    const int tid = threadIdx.x, lane = tid & 31, w = tid >> 5;
    const int op = lane & 15, fh = lane >> 4;

    // stage team_out (coalesced read, pair-layout write)
    const float4* tin4 = reinterpret_cast<const float4*>(g_team + (size_t)b * TT * FF);
    #pragma unroll 2
    for (int i = tid; i < TT * FF / 4; i += 256) {
        int tt = i >> 7, fq = i & 127, f = 4 * fq;
        float4 v = tin4[i];
        if (tt == 8) {
            *reinterpret_cast<float4*>(&ts8[f]) = v;
        } else {
            int sp = tt >> 1, hf = tt & 1;
            tsp[sp * XROW + 2 * (f + 0) + hf] = v.x;
            tsp[sp * XROW + 2 * (f + 1) + hf] = v.y;
            tsp[sp * XROW + 2 * (f + 2) + hf] = v.z;
            tsp[sp * XROW + 2 * (f + 3) + hf] = v.w;
        }
    }
    __syncthreads();

    // two halves of H2: outputs [32*half, 32*half+32)
    #pragma unroll
    for (int half = 0; half < 2; ++half) {
        ull acc00 = 0, acc01 = 0, acc02 = 0, acc03 = 0;
        ull acc10 = 0, acc11 = 0, acc12 = 0, acc13 = 0;
        float acc80 = 0.f, acc81 = 0.f;

        const float4* wq = reinterpret_cast<const float4*>(g_mW1p)
                         + ((size_t)(half * 8 + w) * 16) * 32 + lane;
        const float* xb0 = tsp + 2 * (w * 64 + 2 * fh);
        const float* x8b = ts8 + (w * 64 + 2 * fh);

        #pragma unroll
        for (int g = 0; g < 16; ++g) {
            float4 wv = wq[g * 32];
            const float* xg = xb0 + 8 * g;
            ulonglong2 r0 = *reinterpret_cast<const ulonglong2*>(xg + 0 * XROW);
            ulonglong2 r1 = *reinterpret_cast<const ulonglong2*>(xg + 1 * XROW);
            ulonglong2 r2 = *reinterpret_cast<const ulonglong2*>(xg + 2 * XROW);
            ulonglong2 r3 = *reinterpret_cast<const ulonglong2*>(xg + 3 * XROW);
            float2 x8v = *reinterpret_cast<const float2*>(x8b + 4 * g);
            ull wd;
            wd = dup2(wv.x);
            acc00 = ffma2(r0.x, wd, acc00); acc01 = ffma2(r1.x, wd, acc01);
            acc02 = ffma2(r2.x, wd, acc02); acc03 = ffma2(r3.x, wd, acc03);
            acc80 = fmaf(wv.x, x8v.x, acc80);
            wd = dup2(wv.y);
            acc10 = ffma2(r0.x, wd, acc10); acc11 = ffma2(r1.x, wd, acc11);
            acc12 = ffma2(r2.x, wd, acc12); acc13 = ffma2(r3.x, wd, acc13);
            acc81 = fmaf(wv.y, x8v.x, acc81);
            wd = dup2(wv.z);
            acc00 = ffma2(r0.y, wd, acc00); acc01 = ffma2(r1.y, wd, acc01);
            acc02 = ffma2(r2.y, wd, acc02); acc03 = ffma2(r3.y, wd, acc03);
            acc80 = fmaf(wv.z, x8v.y, acc80);
            wd = dup2(wv.w);
            acc10 = ffma2(r0.y, wd, acc10); acc11 = ffma2(r1.y, wd, acc11);
            acc12 = ffma2(r2.y, wd, acc12); acc13 = ffma2(r3.y, wd, acc13);
            acc81 = fmaf(wv.w, x8v.y, acc81);
        }

        acc00 = fadd2(acc00, __shfl_xor_sync(0xffffffffu, acc00, 16));
        acc01 = fadd2(acc01, __shfl_xor_sync(0xffffffffu, acc01, 16));
        acc02 = fadd2(acc02, __shfl_xor_sync(0xffffffffu, acc02, 16));
        acc03 = fadd2(acc03, __shfl_xor_sync(0xffffffffu, acc03, 16));
        acc10 = fadd2(acc10, __shfl_xor_sync(0xffffffffu, acc10, 16));
        acc11 = fadd2(acc11, __shfl_xor_sync(0xffffffffu, acc11, 16));
        acc12 = fadd2(acc12, __shfl_xor_sync(0xffffffffu, acc12, 16));
        acc13 = fadd2(acc13, __shfl_xor_sync(0xffffffffu, acc13, 16));
        acc80 += __shfl_xor_sync(0xffffffffu, acc80, 16);
        acc81 += __shfl_xor_sync(0xffffffffu, acc81, 16);

        if (fh == 0) {
            int o0 = 2 * op, o1 = 2 * op + 1;
            *reinterpret_cast<ull*>(&psA[((w * 4 + 0) * 32 + o0) * 2]) = acc00;
            *reinterpret_cast<ull*>(&psA[((w * 4 + 1) * 32 + o0) * 2]) = acc01;
            *reinterpret_cast<ull*>(&psA[((w * 4 + 2) * 32 + o0) * 2]) = acc02;
            *reinterpret_cast<ull*>(&psA[((w * 4 + 3) * 32 + o0) * 2]) = acc03;
            ps8[w * 32 + o0] = acc80;
            *reinterpret_cast<ull*>(&psA[((w * 4 + 0) * 32 + o1) * 2]) = acc10;
            *reinterpret_cast<ull*>(&psA[((w * 4 + 1) * 32 + o1) * 2]) = acc11;
            *reinterpret_cast<ull*>(&psA[((w * 4 + 2) * 32 + o1) * 2]) = acc12;
            *reinterpret_cast<ull*>(&psA[((w * 4 + 3) * 32 + o1) * 2]) = acc13;
            ps8[w * 32 + o1] = acc81;
        }
        __syncthreads();

        // finalize this half: sum 8 warp-partials -> pnorm -> msp
        for (int v = tid; v < TT * 32; v += 256) {
            int tt = v >> 5, oo = v & 31;
            float hv = 0.f;
            if (tt == 8) {
                #pragma unroll
                for (int ww = 0; ww < 8; ++ww) hv += ps8[ww * 32 + oo];
            } else {
                int sp = tt >> 1, part = tt & 1;
                #pragma unroll
                for (int ww = 0; ww < 8; ++ww)
                    hv += psA[((ww * 4 + sp) * 32 + oo) * 2 + part];
            }
            int og = 32 * half + oo;
            hv += mb1[og];
            float pn = pnorm1(hv, mgamma[og], mbeta[og]);
            msp[tt * 65 + og] = pn * g_mW2r[og];
        }
        __syncthreads();   // psA safe to reuse for next half
    }

    // softmax over t + penalty (warp 0)
    if (tid < 32) {
        float sc = -3.0e38f;
        if (lane < TT) {
            float s0 = 0.f;
            #pragma unroll
            for (int o = 0; o < H2; ++o) s0 += msp[lane * 65 + o];
            sc = s0;
        }
        float mx = sc;
        #pragma unroll
        for (int d = 16; d; d >>= 1) mx = fmaxf(mx, __shfl_xor_sync(0xffffffffu, mx, d));
        float e = (lane < TT) ? expf(sc - mx) : 0.f;
        float se = e;
        #pragma unroll
        for (int d = 16; d; d >>= 1) se += __shfl_xor_sync(0xffffffffu, se, d);
        float mwq = e / se;

        float tq = (lane < TT) ? g_tq[b * TT + lane] : 0.f;
        float ts = tq;
        #pragma unroll
        for (int d = 16; d; d >>= 1) ts += __shfl_xor_sync(0xffffffffu, ts, d);
        float mean = ts * (1.0f / TT);
        float dv = (lane < TT) ? (tq - mean) * (tq - mean) : 0.f;
        float vs = dv;
        #pragma unroll
        for (int d = 16; d; d >>= 1) vs += __shfl_xor_sync(0xffffffffu, vs, d);
        float var = vs * (1.0f / (TT - 1));
        float nv = var / (mean * mean + 1e-8f);
        float total = cc[0] * (float)(TT * (TT - 1) / 2) + rc[0] * (float)TT
                    + ic[0] * (float)TT * (1.0f + nv);
        float pen = fminf(total, 0.5f);
        if (lane < TT) mwm[lane] = mwq * (1.0f - pen);
    }
    __syncthreads();

    // final output (f-pair per thread)
    {
        float* ob = out + (size_t)b * FF;
        float m0 = mwm[0], m1 = mwm[1], m2 = mwm[2], m3 = mwm[3], m4 = mwm[4],
              m5 = mwm[5], m6 = mwm[6], m7 = mwm[7], m8 = mwm[8];
        int f2 = 2 * tid;
        ulonglong2 u0 = *reinterpret_cast<const ulonglong2*>(&tsp[0 * XROW + 2 * f2]);
        ulonglong2 u1 = *reinterpret_cast<const ulonglong2*>(&tsp[1 * XROW + 2 * f2]);
        ulonglong2 u2 = *reinterpret_cast<const ulonglong2*>(&tsp[2 * XROW + 2 * f2]);
        ulonglong2 u3 = *reinterpret_cast<const ulonglong2*>(&tsp[3 * XROW + 2 * f2]);
        float2 x8v = *reinterpret_cast<const float2*>(&ts8[f2]);
        float o0 = m8 * x8v.x, o1 = m8 * x8v.y;
        float2 a;
        a = u2f(u0.x); o0 = fmaf(m0, a.x, o0); o0 = fmaf(m1, a.y, o0);
        a = u2f(u0.y); o1 = fmaf(m0, a.x, o1); o1 = fmaf(m1, a.y, o1);
        a = u2f(u1.x); o0 = fmaf(m2, a.x, o0); o0 = fmaf(m3, a.y, o0);
        a = u2f(u1.y); o1 = fmaf(m2, a.x, o1); o1 = fmaf(m3, a.y, o1);
        a = u2f(u2.x); o0 = fmaf(m4, a.x, o0); o0 = fmaf(m5, a.y, o0);
        a = u2f(u2.y); o1 = fmaf(m4, a.x, o1); o1 = fmaf(m5, a.y, o1);
        a = u2f(u3.x); o0 = fmaf(m6, a.x, o0); o0 = fmaf(m7, a.y, o0);
        a = u2f(u3.y); o1 = fmaf(m6, a.x, o1); o1 = fmaf(m7, a.y, o1);
        *reinterpret_cast<float2*>(&ob[f2]) = make_float2(o0, o1);
    }
}

// ---------------- launch ----------------
extern "C" void kernel_launch(void* const* d_in, const int* in_sizes, int n_in,
                              void* d_out, int out_size)
{
    const float* path   = (const float*)d_in[0];
    const float* W1     = (const float*)d_in[1];
    const float* b1     = (const float*)d_in[2];
    const float* ang1   = (const float*)d_in[3];
    const float* gamma1 = (const float*)d_in[4];
    const float* beta1  = (const float*)d_in[5];
    const float* W2     = (const float*)d_in[6];
    // d_in[7] = b2 (softmax-invariant, unused)
    const float* ang2   = (const float*)d_in[8];
    const float* mW1    = (const float*)d_in[9];
    const float* mb1    = (const float*)d_in[10];
    const float* mang1  = (const float*)d_in[11];
    const float* mgamma = (const float*)d_in[12];
    const float* mbeta  = (const float*)d_in[13];
    const float* mW2    = (const float*)d_in[14];
    // d_in[15] = mb2 (softmax-invariant, unused)
    const float* mang2  = (const float*)d_in[16];
    const float* cc     = (const float*)d_in[17];
    const float* rc     = (const float*)d_in[18];
    const float* ic     = (const float*)d_in[19];
    (void)n_in; (void)out_size;

    int B = in_sizes[0] / (FF * TT * SS);

    // dummy launches so ncu's bounded capture lands on k1
    kalign<<<1, 32>>>();
    kalign<<<1, 32>>>();

    int prepN = TT * 16384 + TT * H1 + 32768 + H2;
    kprep<<<(prepN + 255) / 256, 256>>>(W1, ang1, W2, ang2, mW1, mang1, mW2, mang2);

    dim3 g1(TT, B);
    k1<<<g1, 256>>>(path, b1, gamma1, beta1);
    k2<<<B, 256>>>(mb1, mgamma, mbeta, cc, rc, ic, (float*)d_out);
}

// round 16
// speedup vs baseline: 1.2430x; 1.2430x over previous
#include <cuda_runtime.h>
#include <cstddef>

#define TT 9
#define SS 9
#define FF 512
#define H1 32
#define H2 64
#define XROW 1032          // floats per t-pair row in k2 (2*FF + 8 pad)
#define BASE7 7.0f

typedef unsigned long long ull;

// ---------------- device scratch ----------------
__device__ float g_W1p [TT * 8 * 16 * 32 * 4];   // rotated W1: [t][w8][g16][lane32][c4]
                                                 // lane=(fh<<4|op), c=(df<<1|do)
                                                 // f = w*64+g*4+fh*2+df, o = op*2+do
__device__ float g_W2r [TT * H1];
__device__ float g_mW1p[2 * 8 * 16 * 32 * 4];    // rotated mW1: [hh2][w8][g16][lane32][c4]
__device__ float g_mW2r[H2];
__device__ float g_team[4096 * TT * FF];
__device__ float g_tq  [4096 * TT];
__device__ float g_sink;

// ---------------- profiling-alignment dummies (ncu capture lands on k1) ----------------
__global__ void kalign() {
    if (threadIdx.x == 0xFFFFFFFFu) g_sink = 0.0f;
}

// ---------------- f32x2 helpers ----------------
__device__ __forceinline__ ull ffma2(ull a, ull b, ull c) {
    ull d;
    asm("fma.rn.f32x2 %0, %1, %2, %3;" : "=l"(d) : "l"(a), "l"(b), "l"(c));
    return d;
}
__device__ __forceinline__ ull fadd2(ull a, ull b) {
    ull d;
    asm("add.rn.f32x2 %0, %1, %2;" : "=l"(d) : "l"(a), "l"(b));
    return d;
}
__device__ __forceinline__ ull dup2(float x) {
    ull r;
    asm("mov.b64 %0, {%1, %1};" : "=l"(r) : "f"(x));
    return r;
}
__device__ __forceinline__ float2 u2f(ull r) {
    float2 v;
    asm("mov.b64 {%0, %1}, %2;" : "=f"(v.x), "=f"(v.y) : "l"(r));
    return v;
}

__device__ __forceinline__ float pnorm1(float h, float g, float b) {
    float m = h - BASE7 * floorf(h * (1.0f / BASE7));
    return g * ((m - 3.5f) * (1.0f / 3.5f)) + b;
}

// rotate-absorb: coeff of x_f in dot(rot(x), Wrow)
__device__ __forceinline__ float rotv(const float* __restrict__ Wrow,
                                      const float* __restrict__ ang,
                                      int f, int nplanes) {
    if (f >= 2 * nplanes) return Wrow[f];
    int p = f >> 1; float a = ang[p];
    float c = cosf(a), s = sinf(a);
    float w0 = Wrow[2 * p], w1 = Wrow[2 * p + 1];
    return (f & 1) ? (c * w1 - s * w0) : (c * w0 + s * w1);
}

// ---------------- prep: rotate + re-tile weights (R14-proven) ----------------
__global__ void kprep(const float* __restrict__ W1, const float* __restrict__ ang1,
                      const float* __restrict__ W2, const float* __restrict__ ang2,
                      const float* __restrict__ mW1, const float* __restrict__ mang1,
                      const float* __restrict__ mW2, const float* __restrict__ mang2)
{
    int idx = blockIdx.x * 256 + threadIdx.x;
    const int N1 = TT * 16384;     // g_W1p
    const int N2 = TT * H1;        // g_W2r
    const int N3 = 32768;          // g_mW1p
    const int N4 = H2;             // g_mW2r
    if (idx < N1) {
        int c    =  idx        & 3;
        int lane = (idx >> 2)  & 31;
        int g    = (idx >> 7)  & 15;
        int w    = (idx >> 11) & 7;
        int t    =  idx >> 14;
        int op = lane & 15, fh = lane >> 4;
        int df = c >> 1, dd = c & 1;
        int f = w * 64 + g * 4 + fh * 2 + df;
        int o = op * 2 + dd;
        g_W1p[idx] = rotv(W1 + ((size_t)t * H1 + o) * FF, ang1 + 2 * t, f, 2);
    } else if (idx < N1 + N2) {
        int jj = idx - N1; int t = jj / H1, o = jj - t * H1;
        g_W2r[jj] = rotv(W2 + t * H1, ang2 + 2 * t, o, 2);
    } else if (idx < N1 + N2 + N3) {
        int jj = idx - N1 - N2;
        int c    =  jj        & 3;
        int lane = (jj >> 2)  & 31;
        int g    = (jj >> 7)  & 15;
        int w    = (jj >> 11) & 7;
        int hh   = (jj >> 14) & 1;
        int op = lane & 15, fh = lane >> 4;
        int df = c >> 1, dd = c & 1;
        int f = w * 64 + g * 4 + fh * 2 + df;
        int o = 32 * hh + op * 2 + dd;
        g_mW1p[jj] = rotv(mW1 + (size_t)o * FF, mang1, f, 4);
    } else if (idx < N1 + N2 + N3 + N4) {
        int o = idx - N1 - N2 - N3;
        g_mW2r[o] = rotv(mW2, mang2, o, 2);
    }
}

// ---------------- kernel 1: per (b,t) — o-pair lanes, row-per-f x layout ----------------
__global__ __launch_bounds__(256, 5) void k1(const float* __restrict__ path,
                                             const float* __restrict__ b1,
                                             const float* __restrict__ gamma1,
                                             const float* __restrict__ beta1)
{
    __shared__ float xraw[FF * 8];           // x rows: [f][s0..7], 32B per f
    __shared__ float xs8[FF + 8];            // s=8 column
    __shared__ float psA[8 * 4 * 32 * 2];    // warp partials: [w][sp][o]{lo,hi}
    __shared__ float ps8[8 * 32];            // warp partials s=8: [w][o]
    __shared__ float scp[SS * 33];           // score partials
    __shared__ float qsm[16];

    const int t = blockIdx.x, b = blockIdx.y;
    const int tid = threadIdx.x, lane = tid & 31, w = tid >> 5;
    const int op = lane & 15, fh = lane >> 4;
    (void)op;

    // stage x: row-per-f layout (incremental f,s walker; STS nearly sequential)
    {
        const float* xb = path + (size_t)b * (FF * TT * SS) + t * SS;
        int f = tid / 9;
        int s = tid - f * 9;
        const float* p = xb + f * (TT * SS) + s;
        #pragma unroll
        for (int it = 0; it < 18; ++it) {
            float v = *p;
            if (s == 8) xs8[f] = v;
            else xraw[f * 8 + s] = v;
            s += 4; f += 28;
            if (s >= 9) { s -= 9; f += 1; p += 29 * (TT * SS) - 5; }
            else        {                p += 28 * (TT * SS) + 4; }
        }
    }
    __syncthreads();

    // mainloop: lane owns o-pair {2op, 2op+1}; warp w covers f in [64w, 64w+64);
    // lane's f-pair: f = 64w + 4g + 2fh + {0,1}
    ull acc00 = 0, acc01 = 0, acc02 = 0, acc03 = 0;   // do=0, sp 0..3
    ull acc10 = 0, acc11 = 0, acc12 = 0, acc13 = 0;   // do=1
    float acc80 = 0.f, acc81 = 0.f;

    const float4* wq = reinterpret_cast<const float4*>(g_W1p)
                     + ((size_t)(t * 8 + w) * 16) * 32 + lane;
    const float* xb0 = xraw + 8 * (w * 64 + 2 * fh);
    const float* x8b = xs8 + (w * 64 + 2 * fh);

    #pragma unroll
    for (int g = 0; g < 16; ++g) {
        float4 wv = wq[g * 32];
        const float* xg = xb0 + 32 * g;
        // f's s-pairs: X=(s0s1, s2s3), X2=(s4s5, s6s7); f+1's: Y, Y2
        ulonglong2 X  = *reinterpret_cast<const ulonglong2*>(xg);
        ulonglong2 X2 = *reinterpret_cast<const ulonglong2*>(xg + 4);
        ulonglong2 Y  = *reinterpret_cast<const ulonglong2*>(xg + 8);
        ulonglong2 Y2 = *reinterpret_cast<const ulonglong2*>(xg + 12);
        float2 x8v = *reinterpret_cast<const float2*>(x8b + 4 * g);
        ull wd;
        // df = 0 (f)
        wd = dup2(wv.x);
        acc00 = ffma2(X.x, wd, acc00); acc01 = ffma2(X.y, wd, acc01);
        acc02 = ffma2(X2.x, wd, acc02); acc03 = ffma2(X2.y, wd, acc03);
        acc80 = fmaf(wv.x, x8v.x, acc80);
        wd = dup2(wv.y);
        acc10 = ffma2(X.x, wd, acc10); acc11 = ffma2(X.y, wd, acc11);
        acc12 = ffma2(X2.x, wd, acc12); acc13 = ffma2(X2.y, wd, acc13);
        acc81 = fmaf(wv.y, x8v.x, acc81);
        // df = 1 (f+1)
        wd = dup2(wv.z);
        acc00 = ffma2(Y.x, wd, acc00); acc01 = ffma2(Y.y, wd, acc01);
        acc02 = ffma2(Y2.x, wd, acc02); acc03 = ffma2(Y2.y, wd, acc03);
        acc80 = fmaf(wv.z, x8v.y, acc80);
        wd = dup2(wv.w);
        acc10 = ffma2(Y.x, wd, acc10); acc11 = ffma2(Y.y, wd, acc11);
        acc12 = ffma2(Y2.x, wd, acc12); acc13 = ffma2(Y2.y, wd, acc13);
        acc81 = fmaf(wv.w, x8v.y, acc81);
    }

    // combine fh halves (one xor-16 round), lanes 0..15 hold warp totals
    acc00 = fadd2(acc00, __shfl_xor_sync(0xffffffffu, acc00, 16));
    acc01 = fadd2(acc01, __shfl_xor_sync(0xffffffffu, acc01, 16));
    acc02 = fadd2(acc02, __shfl_xor_sync(0xffffffffu, acc02, 16));
    acc03 = fadd2(acc03, __shfl_xor_sync(0xffffffffu, acc03, 16));
    acc10 = fadd2(acc10, __shfl_xor_sync(0xffffffffu, acc10, 16));
    acc11 = fadd2(acc11, __shfl_xor_sync(0xffffffffu, acc11, 16));
    acc12 = fadd2(acc12, __shfl_xor_sync(0xffffffffu, acc12, 16));
    acc13 = fadd2(acc13, __shfl_xor_sync(0xffffffffu, acc13, 16));
    acc80 += __shfl_xor_sync(0xffffffffu, acc80, 16);
    acc81 += __shfl_xor_sync(0xffffffffu, acc81, 16);

    if (fh == 0) {
        int o0 = 2 * (lane & 15), o1 = o0 + 1;
        *reinterpret_cast<ull*>(&psA[((w * 4 + 0) * 32 + o0) * 2]) = acc00;
        *reinterpret_cast<ull*>(&psA[((w * 4 + 1) * 32 + o0) * 2]) = acc01;
        *reinterpret_cast<ull*>(&psA[((w * 4 + 2) * 32 + o0) * 2]) = acc02;
        *reinterpret_cast<ull*>(&psA[((w * 4 + 3) * 32 + o0) * 2]) = acc03;
        ps8[w * 32 + o0] = acc80;
        *reinterpret_cast<ull*>(&psA[((w * 4 + 0) * 32 + o1) * 2]) = acc10;
        *reinterpret_cast<ull*>(&psA[((w * 4 + 1) * 32 + o1) * 2]) = acc11;
        *reinterpret_cast<ull*>(&psA[((w * 4 + 2) * 32 + o1) * 2]) = acc12;
        *reinterpret_cast<ull*>(&psA[((w * 4 + 3) * 32 + o1) * 2]) = acc13;
        ps8[w * 32 + o1] = acc81;
    }
    __syncthreads();

    // finalize: sum 8 warp-partials -> h -> pnorm -> score partials
    for (int v = tid; v < SS * H1; v += 256) {
        int s = v >> 5, o = v & 31;
        float hh = 0.f;
        if (s == 8) {
            #pragma unroll
            for (int ww = 0; ww < 8; ++ww) hh += ps8[ww * 32 + o];
        } else {
            int sp = s >> 1, part = s & 1;
            #pragma unroll
            for (int ww = 0; ww < 8; ++ww)
                hh += psA[((ww * 4 + sp) * 32 + o) * 2 + part];
        }
        hh += b1[t * H1 + o];
        float pn = pnorm1(hh, gamma1[t * H1 + o], beta1[t * H1 + o]);
        scp[s * 33 + o] = pn * g_W2r[t * H1 + o];
    }
    __syncthreads();

    // softmax over s (warp 0)
    if (tid < 32) {
        float sc = -3.0e38f;
        if (lane < SS) {
            float s0 = 0.f;
            #pragma unroll
            for (int o = 0; o < H1; ++o) s0 += scp[lane * 33 + o];
            sc = s0;
        }
        float mx = sc;
        #pragma unroll
        for (int d = 16; d; d >>= 1) mx = fmaxf(mx, __shfl_xor_sync(0xffffffffu, mx, d));
        float e = (lane < SS) ? expf(sc - mx) : 0.f;
        float se = e;
        #pragma unroll
        for (int d = 16; d; d >>= 1) se += __shfl_xor_sync(0xffffffffu, se, d);
        float q = e / se;
        float qt = q;
        #pragma unroll
        for (int d = 16; d; d >>= 1) qt += __shfl_xor_sync(0xffffffffu, qt, d);
        if (lane < SS) qsm[lane] = q;
        if (lane == 0) g_tq[b * TT + t] = qt * (1.0f / SS);
    }
    __syncthreads();

    // team_out[f] = sum_s q[s] * x[s][f]  (per f; rows are contiguous)
    {
        float* tout = g_team + ((size_t)b * TT + t) * FF;
        float q0 = qsm[0], q1 = qsm[1], q2 = qsm[2], q3 = qsm[3], q4 = qsm[4],
              q5 = qsm[5], q6 = qsm[6], q7 = qsm[7], q8 = qsm[8];
        #pragma unroll
        for (int it = 0; it < 2; ++it) {
            int f = tid + it * 256;
            const float* xg = xraw + 8 * f;
            float4 X0 = *reinterpret_cast<const float4*>(xg);
            float4 X1 = *reinterpret_cast<const float4*>(xg + 4);
            float o = q8 * xs8[f];
            o = fmaf(q0, X0.x, o); o = fmaf(q1, X0.y, o);
            o = fmaf(q2, X0.z, o); o = fmaf(q3, X0.w, o);
            o = fmaf(q4, X1.x, o); o = fmaf(q5, X1.y, o);
            o = fmaf(q6, X1.z, o); o = fmaf(q7, X1.w, o);
            tout[f] = o;
        }
    }
}

// ---------------- kernel 2: per b — o-pair lanes, two H2 halves (R14-proven) ----------------
__global__ __launch_bounds__(256, 4) void k2(const float* __restrict__ mb1,
                                             const float* __restrict__ mgamma,
                                             const float* __restrict__ mbeta,
                                             const float* __restrict__ cc,
                                             const float* __restrict__ rc,
                                             const float* __restrict__ ic,
                                             float* __restrict__ out)
{
    __shared__ float tsp[4 * XROW];          // team t-pair rows
    __shared__ float ts8[FF + 8];            // t=8 row
    __shared__ float psA[8 * 4 * 32 * 2];    // warp partials (reused per half)
    __shared__ float ps8[8 * 32];
    __shared__ float msp[9 * 65];            // score partials (full H2)
    __shared__ float mwm[16];

    const int b = blockIdx.x;
    const int tid = threadIdx.x, lane = tid & 31, w = tid >> 5;
    const int op = lane & 15, fh = lane >> 4;

    // stage team_out (coalesced read, pair-layout write)
    const float4* tin4 = reinterpret_cast<const float4*>(g_team + (size_t)b * TT * FF);
    #pragma unroll 2
    for (int i = tid; i < TT * FF / 4; i += 256) {
        int tt = i >> 7, fq = i & 127, f = 4 * fq;
        float4 v = tin4[i];
        if (tt == 8) {
            *reinterpret_cast<float4*>(&ts8[f]) = v;
        } else {
            int sp = tt >> 1, hf = tt & 1;
            tsp[sp * XROW + 2 * (f + 0) + hf] = v.x;
            tsp[sp * XROW + 2 * (f + 1) + hf] = v.y;
            tsp[sp * XROW + 2 * (f + 2) + hf] = v.z;
            tsp[sp * XROW + 2 * (f + 3) + hf] = v.w;
        }
    }
    __syncthreads();

    // two halves of H2: outputs [32*half, 32*half+32)
    #pragma unroll
    for (int half = 0; half < 2; ++half) {
        ull acc00 = 0, acc01 = 0, acc02 = 0, acc03 = 0;
        ull acc10 = 0, acc11 = 0, acc12 = 0, acc13 = 0;
        float acc80 = 0.f, acc81 = 0.f;

        const float4* wq = reinterpret_cast<const float4*>(g_mW1p)
                         + ((size_t)(half * 8 + w) * 16) * 32 + lane;
        const float* xb0 = tsp + 2 * (w * 64 + 2 * fh);
        const float* x8b = ts8 + (w * 64 + 2 * fh);

        #pragma unroll
        for (int g = 0; g < 16; ++g) {
            float4 wv = wq[g * 32];
            const float* xg = xb0 + 8 * g;
            ulonglong2 r0 = *reinterpret_cast<const ulonglong2*>(xg + 0 * XROW);
            ulonglong2 r1 = *reinterpret_cast<const ulonglong2*>(xg + 1 * XROW);
            ulonglong2 r2 = *reinterpret_cast<const ulonglong2*>(xg + 2 * XROW);
            ulonglong2 r3 = *reinterpret_cast<const ulonglong2*>(xg + 3 * XROW);
            float2 x8v = *reinterpret_cast<const float2*>(x8b + 4 * g);
            ull wd;
            wd = dup2(wv.x);
            acc00 = ffma2(r0.x, wd, acc00); acc01 = ffma2(r1.x, wd, acc01);
            acc02 = ffma2(r2.x, wd, acc02); acc03 = ffma2(r3.x, wd, acc03);
            acc80 = fmaf(wv.x, x8v.x, acc80);
            wd = dup2(wv.y);
            acc10 = ffma2(r0.x, wd, acc10); acc11 = ffma2(r1.x, wd, acc11);
            acc12 = ffma2(r2.x, wd, acc12); acc13 = ffma2(r3.x, wd, acc13);
            acc81 = fmaf(wv.y, x8v.x, acc81);
            wd = dup2(wv.z);
            acc00 = ffma2(r0.y, wd, acc00); acc01 = ffma2(r1.y, wd, acc01);
            acc02 = ffma2(r2.y, wd, acc02); acc03 = ffma2(r3.y, wd, acc03);
            acc80 = fmaf(wv.z, x8v.y, acc80);
            wd = dup2(wv.w);
            acc10 = ffma2(r0.y, wd, acc10); acc11 = ffma2(r1.y, wd, acc11);
            acc12 = ffma2(r2.y, wd, acc12); acc13 = ffma2(r3.y, wd, acc13);
            acc81 = fmaf(wv.w, x8v.y, acc81);
        }

        acc00 = fadd2(acc00, __shfl_xor_sync(0xffffffffu, acc00, 16));
        acc01 = fadd2(acc01, __shfl_xor_sync(0xffffffffu, acc01, 16));
        acc02 = fadd2(acc02, __shfl_xor_sync(0xffffffffu, acc02, 16));
        acc03 = fadd2(acc03, __shfl_xor_sync(0xffffffffu, acc03, 16));
        acc10 = fadd2(acc10, __shfl_xor_sync(0xffffffffu, acc10, 16));
        acc11 = fadd2(acc11, __shfl_xor_sync(0xffffffffu, acc11, 16));
        acc12 = fadd2(acc12, __shfl_xor_sync(0xffffffffu, acc12, 16));
        acc13 = fadd2(acc13, __shfl_xor_sync(0xffffffffu, acc13, 16));
        acc80 += __shfl_xor_sync(0xffffffffu, acc80, 16);
        acc81 += __shfl_xor_sync(0xffffffffu, acc81, 16);

        if (fh == 0) {
            int o0 = 2 * op, o1 = 2 * op + 1;
            *reinterpret_cast<ull*>(&psA[((w * 4 + 0) * 32 + o0) * 2]) = acc00;
            *reinterpret_cast<ull*>(&psA[((w * 4 + 1) * 32 + o0) * 2]) = acc01;
            *reinterpret_cast<ull*>(&psA[((w * 4 + 2) * 32 + o0) * 2]) = acc02;
            *reinterpret_cast<ull*>(&psA[((w * 4 + 3) * 32 + o0) * 2]) = acc03;
            ps8[w * 32 + o0] = acc80;
            *reinterpret_cast<ull*>(&psA[((w * 4 + 0) * 32 + o1) * 2]) = acc10;
            *reinterpret_cast<ull*>(&psA[((w * 4 + 1) * 32 + o1) * 2]) = acc11;
            *reinterpret_cast<ull*>(&psA[((w * 4 + 2) * 32 + o1) * 2]) = acc12;
            *reinterpret_cast<ull*>(&psA[((w * 4 + 3) * 32 + o1) * 2]) = acc13;
            ps8[w * 32 + o1] = acc81;
        }
        __syncthreads();

        // finalize this half: sum 8 warp-partials -> pnorm -> msp
        for (int v = tid; v < TT * 32; v += 256) {
            int tt = v >> 5, oo = v & 31;
            float hv = 0.f;
            if (tt == 8) {
                #pragma unroll
                for (int ww = 0; ww < 8; ++ww) hv += ps8[ww * 32 + oo];
            } else {
                int sp = tt >> 1, part = tt & 1;
                #pragma unroll
                for (int ww = 0; ww < 8; ++ww)
                    hv += psA[((ww * 4 + sp) * 32 + oo) * 2 + part];
            }
            int og = 32 * half + oo;
            hv += mb1[og];
            float pn = pnorm1(hv, mgamma[og], mbeta[og]);
            msp[tt * 65 + og] = pn * g_mW2r[og];
        }
        __syncthreads();   // psA safe to reuse for next half
    }

    // softmax over t + penalty (warp 0)
    if (tid < 32) {
        float sc = -3.0e38f;
        if (lane < TT) {
            float s0 = 0.f;
            #pragma unroll
            for (int o = 0; o < H2; ++o) s0 += msp[lane * 65 + o];
            sc = s0;
        }
        float mx = sc;
        #pragma unroll
        for (int d = 16; d; d >>= 1) mx = fmaxf(mx, __shfl_xor_sync(0xffffffffu, mx, d));
        float e = (lane < TT) ? expf(sc - mx) : 0.f;
        float se = e;
        #pragma unroll
        for (int d = 16; d; d >>= 1) se += __shfl_xor_sync(0xffffffffu, se, d);
        float mwq = e / se;

        float tq = (lane < TT) ? g_tq[b * TT + lane] : 0.f;
        float ts = tq;
        #pragma unroll
        for (int d = 16; d; d >>= 1) ts += __shfl_xor_sync(0xffffffffu, ts, d);
        float mean = ts * (1.0f / TT);
        float dv = (lane < TT) ? (tq - mean) * (tq - mean) : 0.f;
        float vs = dv;
        #pragma unroll
        for (int d = 16; d; d >>= 1) vs += __shfl_xor_sync(0xffffffffu, vs, d);
        float var = vs * (1.0f / (TT - 1));
        float nv = var / (mean * mean + 1e-8f);
        float total = cc[0] * (float)(TT * (TT - 1) / 2) + rc[0] * (float)TT
                    + ic[0] * (float)TT * (1.0f + nv);
        float pen = fminf(total, 0.5f);
        if (lane < TT) mwm[lane] = mwq * (1.0f - pen);
    }
    __syncthreads();

    // final output (f-pair per thread)
    {
        float* ob = out + (size_t)b * FF;
        float m0 = mwm[0], m1 = mwm[1], m2 = mwm[2], m3 = mwm[3], m4 = mwm[4],
              m5 = mwm[5], m6 = mwm[6], m7 = mwm[7], m8 = mwm[8];
        int f2 = 2 * tid;
        ulonglong2 u0 = *reinterpret_cast<const ulonglong2*>(&tsp[0 * XROW + 2 * f2]);
        ulonglong2 u1 = *reinterpret_cast<const ulonglong2*>(&tsp[1 * XROW + 2 * f2]);
        ulonglong2 u2 = *reinterpret_cast<const ulonglong2*>(&tsp[2 * XROW + 2 * f2]);
        ulonglong2 u3 = *reinterpret_cast<const ulonglong2*>(&tsp[3 * XROW + 2 * f2]);
        float2 x8v = *reinterpret_cast<const float2*>(&ts8[f2]);
        float o0 = m8 * x8v.x, o1 = m8 * x8v.y;
        float2 a;
        a = u2f(u0.x); o0 = fmaf(m0, a.x, o0); o0 = fmaf(m1, a.y, o0);
        a = u2f(u0.y); o1 = fmaf(m0, a.x, o1); o1 = fmaf(m1, a.y, o1);
        a = u2f(u1.x); o0 = fmaf(m2, a.x, o0); o0 = fmaf(m3, a.y, o0);
        a = u2f(u1.y); o1 = fmaf(m2, a.x, o1); o1 = fmaf(m3, a.y, o1);
        a = u2f(u2.x); o0 = fmaf(m4, a.x, o0); o0 = fmaf(m5, a.y, o0);
        a = u2f(u2.y); o1 = fmaf(m4, a.x, o1); o1 = fmaf(m5, a.y, o1);
        a = u2f(u3.x); o0 = fmaf(m6, a.x, o0); o0 = fmaf(m7, a.y, o0);
        a = u2f(u3.y); o1 = fmaf(m6, a.x, o1); o1 = fmaf(m7, a.y, o1);
        *reinterpret_cast<float2*>(&ob[f2]) = make_float2(o0, o1);
    }
}

// ---------------- launch ----------------
extern "C" void kernel_launch(void* const* d_in, const int* in_sizes, int n_in,
                              void* d_out, int out_size)
{
    const float* path   = (const float*)d_in[0];
    const float* W1     = (const float*)d_in[1];
    const float* b1     = (const float*)d_in[2];
    const float* ang1   = (const float*)d_in[3];
    const float* gamma1 = (const float*)d_in[4];
    const float* beta1  = (const float*)d_in[5];
    const float* W2     = (const float*)d_in[6];
    // d_in[7] = b2 (softmax-invariant, unused)
    const float* ang2   = (const float*)d_in[8];
    const float* mW1    = (const float*)d_in[9];
    const float* mb1    = (const float*)d_in[10];
    const float* mang1  = (const float*)d_in[11];
    const float* mgamma = (const float*)d_in[12];
    const float* mbeta  = (const float*)d_in[13];
    const float* mW2    = (const float*)d_in[14];
    // d_in[15] = mb2 (softmax-invariant, unused)
    const float* mang2  = (const float*)d_in[16];
    const float* cc     = (const float*)d_in[17];
    const float* rc     = (const float*)d_in[18];
    const float* ic     = (const float*)d_in[19];
    (void)n_in; (void)out_size;

    int B = in_sizes[0] / (FF * TT * SS);

    // dummy launches so ncu's bounded capture lands on k1
    kalign<<<1, 32>>>();
    kalign<<<1, 32>>>();

    int prepN = TT * 16384 + TT * H1 + 32768 + H2;
    kprep<<<(prepN + 255) / 256, 256>>>(W1, ang1, W2, ang2, mW1, mang1, mW2, mang2);

    dim3 g1(TT, B);
    k1<<<g1, 256>>>(path, b1, gamma1, beta1);
    k2<<<B, 256>>>(mb1, mgamma, mbeta, cc, rc, ic, (float*)d_out);
}